// round 2
// baseline (speedup 1.0000x reference)
#include <cuda_runtime.h>
#include <cuda_bf16.h>

// PreprocessLayerTorch: MIC pairwise distances + shifts + element one-hot.
// Output layout (float32), matching reference return order, flattened:
//   [0, n*4)                      onehot (n, 4)
//   [n*4, n*4 + n*n)              dist_masked (n, n)
//   [n*4 + n*n, n*4 + n*n + 3nn)  shift (n, n, 3)

#define NMAX 8192
__device__ float g_fx[NMAX];
__device__ float g_fy[NMAX];
__device__ float g_fz[NMAX];

__global__ void onehot_kernel(const int* __restrict__ elems,
                              float* __restrict__ out, int n) {
    int idx = blockIdx.x * blockDim.x + threadIdx.x;
    if (idx >= n * 4) return;
    int i = idx >> 2;
    int t = idx & 3;
    int types[4] = {1, 6, 7, 8};
    out[idx] = (elems[i] == types[t]) ? 1.0f : 0.0f;
}

__global__ void frac_kernel(const float* __restrict__ coord,
                            const float* __restrict__ cell, int n) {
    int i = blockIdx.x * blockDim.x + threadIdx.x;
    if (i >= n) return;

    float c00 = cell[0], c01 = cell[1], c02 = cell[2];
    float c10 = cell[3], c11 = cell[4], c12 = cell[5];
    float c20 = cell[6], c21 = cell[7], c22 = cell[8];

    float det = c00 * (c11 * c22 - c12 * c21)
              - c01 * (c10 * c22 - c12 * c20)
              + c02 * (c10 * c21 - c11 * c20);
    float id = 1.0f / det;

    float i00 =  (c11 * c22 - c12 * c21) * id;
    float i01 = -(c01 * c22 - c02 * c21) * id;
    float i02 =  (c01 * c12 - c02 * c11) * id;
    float i10 = -(c10 * c22 - c12 * c20) * id;
    float i11 =  (c00 * c22 - c02 * c20) * id;
    float i12 = -(c00 * c12 - c02 * c10) * id;
    float i20 =  (c10 * c21 - c11 * c20) * id;
    float i21 = -(c00 * c21 - c01 * c20) * id;
    float i22 =  (c00 * c11 - c01 * c10) * id;

    float x = coord[3 * i + 0];
    float y = coord[3 * i + 1];
    float z = coord[3 * i + 2];

    float fx = x * i00 + y * i10 + z * i20;
    float fy = x * i01 + y * i11 + z * i21;
    float fz = x * i02 + y * i12 + z * i22;

    fx -= floorf(fx);
    fy -= floorf(fy);
    fz -= floorf(fz);

    g_fx[i] = fx;
    g_fy[i] = fy;
    g_fz[i] = fz;
}

// Each thread handles 8 consecutive j's (two float4 packs), producing
// 2 dist float4 stores + 6 shift float4 stores, all issued back-to-back
// with streaming (.cs) hints for maximum store MLP.
__global__ __launch_bounds__(256)
void pair_kernel(const float* __restrict__ cell,
                 float* __restrict__ dist_out,
                 float* __restrict__ shift_out, int n) {
    int i = blockIdx.y;
    int j0 = (blockIdx.x * blockDim.x + threadIdx.x) * 8;
    if (j0 >= n) return;

    float c00 = __ldg(cell + 0), c01 = __ldg(cell + 1), c02 = __ldg(cell + 2);
    float c10 = __ldg(cell + 3), c11 = __ldg(cell + 4), c12 = __ldg(cell + 5);
    float c20 = __ldg(cell + 6), c21 = __ldg(cell + 7), c22 = __ldg(cell + 8);

    float fxi = g_fx[i], fyi = g_fy[i], fzi = g_fz[i];

    long long base = (long long)i * n + j0;
    float* dp = dist_out + base;
    float* sp = shift_out + base * 3;  // 16B aligned (j0 % 8 == 0)

    float dvals[8];
    float svals[24];

#pragma unroll
    for (int p = 0; p < 2; p++) {
        int jj = j0 + p * 4;
        bool active = (jj < n);   // n % 4 == 0, so full packs only
        if (!active) {
            // fill with zeros so stores below are well-defined (guarded anyway)
            continue;
        }
        float4 fxj = *reinterpret_cast<const float4*>(g_fx + jj);
        float4 fyj = *reinterpret_cast<const float4*>(g_fy + jj);
        float4 fzj = *reinterpret_cast<const float4*>(g_fz + jj);

        float fxs[4] = {fxj.x, fxj.y, fxj.z, fxj.w};
        float fys[4] = {fyj.x, fyj.y, fyj.z, fyj.w};
        float fzs[4] = {fzj.x, fzj.y, fzj.z, fzj.w};

#pragma unroll
        for (int k = 0; k < 4; k++) {
            float dfx = fxs[k] - fxi;
            float dfy = fys[k] - fyi;
            float dfz = fzs[k] - fzi;

            float sx = -rintf(dfx);
            float sy = -rintf(dfy);
            float sz = -rintf(dfz);
            dfx += sx;
            dfy += sy;
            dfz += sz;

            float dx = dfx * c00 + dfy * c10 + dfz * c20;
            float dy = dfx * c01 + dfy * c11 + dfz * c21;
            float dz = dfx * c02 + dfy * c12 + dfz * c22;

            float d2 = dx * dx + dy * dy + dz * dz;
            bool m = (d2 > 0.0f) && (d2 < 25.0f);  // RC = 5.0
            int q = p * 4 + k;
            dvals[q] = m ? sqrtf(d2) : 0.0f;
            svals[3 * q + 0] = sx;
            svals[3 * q + 1] = sy;
            svals[3 * q + 2] = sz;
        }
    }

    // Batched streaming stores: 2x dist + 6x shift float4s.
    if (j0 + 4 <= n) {
        __stcs(reinterpret_cast<float4*>(dp),
               make_float4(dvals[0], dvals[1], dvals[2], dvals[3]));
        __stcs(reinterpret_cast<float4*>(sp) + 0,
               make_float4(svals[0], svals[1], svals[2], svals[3]));
        __stcs(reinterpret_cast<float4*>(sp) + 1,
               make_float4(svals[4], svals[5], svals[6], svals[7]));
        __stcs(reinterpret_cast<float4*>(sp) + 2,
               make_float4(svals[8], svals[9], svals[10], svals[11]));
    }
    if (j0 + 8 <= n) {
        __stcs(reinterpret_cast<float4*>(dp) + 1,
               make_float4(dvals[4], dvals[5], dvals[6], dvals[7]));
        __stcs(reinterpret_cast<float4*>(sp) + 3,
               make_float4(svals[12], svals[13], svals[14], svals[15]));
        __stcs(reinterpret_cast<float4*>(sp) + 4,
               make_float4(svals[16], svals[17], svals[18], svals[19]));
        __stcs(reinterpret_cast<float4*>(sp) + 5,
               make_float4(svals[20], svals[21], svals[22], svals[23]));
    }
}

extern "C" void kernel_launch(void* const* d_in, const int* in_sizes, int n_in,
                              void* d_out, int out_size) {
    const float* coord = (const float*)d_in[0];   // (n, 3) float32
    const float* cell  = (const float*)d_in[1];   // (3, 3) float32
    const int*   elems = (const int*)d_in[2];     // (n,)   int32

    int n = in_sizes[0] / 3;

    float* out       = (float*)d_out;
    float* dist_out  = out + (long long)n * 4;      // n*n
    float* shift_out = dist_out + (long long)n * n; // n*n*3

    // 1) one-hot
    {
        int total = n * 4;
        int threads = 256;
        int blocks = (total + threads - 1) / threads;
        onehot_kernel<<<blocks, threads>>>(elems, out, n);
    }

    // 2) fractional coords (wrapped)
    {
        int threads = 256;
        int blocks = (n + threads - 1) / threads;
        frac_kernel<<<blocks, threads>>>(coord, cell, n);
    }

    // 3) pairwise dist + shift
    {
        const int THREADS = 256;
        int jblocks = (n + THREADS * 8 - 1) / (THREADS * 8);
        dim3 grid(jblocks, n);
        pair_kernel<<<grid, THREADS>>>(cell, dist_out, shift_out, n);
    }
}

// round 3
// speedup vs baseline: 1.7393x; 1.7393x over previous
#include <cuda_runtime.h>
#include <cuda_bf16.h>

// PreprocessLayerTorch: MIC pairwise distances + shifts + element one-hot.
// Output layout (float32), flattened:
//   [0, n*4)                      onehot (n, 4)
//   [n*4, n*4 + n*n)              dist_masked (n, n)
//   [n*4 + n*n, +3nn)             shift (n, n, 3)

#define NMAX 8192
__device__ float g_fx[NMAX];
__device__ float g_fy[NMAX];
__device__ float g_fz[NMAX];

// Fused: fractional coords (wrapped) + onehot (one float4 store per atom).
__global__ void frac_onehot_kernel(const float* __restrict__ coord,
                                   const float* __restrict__ cell,
                                   const int* __restrict__ elems,
                                   float* __restrict__ onehot_out, int n) {
    int i = blockIdx.x * blockDim.x + threadIdx.x;
    if (i >= n) return;

    float c00 = cell[0], c01 = cell[1], c02 = cell[2];
    float c10 = cell[3], c11 = cell[4], c12 = cell[5];
    float c20 = cell[6], c21 = cell[7], c22 = cell[8];

    float det = c00 * (c11 * c22 - c12 * c21)
              - c01 * (c10 * c22 - c12 * c20)
              + c02 * (c10 * c21 - c11 * c20);
    float id = 1.0f / det;

    float i00 =  (c11 * c22 - c12 * c21) * id;
    float i01 = -(c01 * c22 - c02 * c21) * id;
    float i02 =  (c01 * c12 - c02 * c11) * id;
    float i10 = -(c10 * c22 - c12 * c20) * id;
    float i11 =  (c00 * c22 - c02 * c20) * id;
    float i12 = -(c00 * c12 - c02 * c10) * id;
    float i20 =  (c10 * c21 - c11 * c20) * id;
    float i21 = -(c00 * c21 - c01 * c20) * id;
    float i22 =  (c00 * c11 - c01 * c10) * id;

    float x = coord[3 * i + 0];
    float y = coord[3 * i + 1];
    float z = coord[3 * i + 2];

    float fx = x * i00 + y * i10 + z * i20;
    float fy = x * i01 + y * i11 + z * i21;
    float fz = x * i02 + y * i12 + z * i22;

    fx -= floorf(fx);
    fy -= floorf(fy);
    fz -= floorf(fz);

    g_fx[i] = fx;
    g_fy[i] = fy;
    g_fz[i] = fz;

    int e = elems[i];
    *reinterpret_cast<float4*>(onehot_out + 4 * i) =
        make_float4(e == 1 ? 1.0f : 0.0f, e == 6 ? 1.0f : 0.0f,
                    e == 7 ? 1.0f : 0.0f, e == 8 ? 1.0f : 0.0f);
}

// One block handles 1024 consecutive j's of one row i.
// dist: direct warp-contiguous float4 stores.
// shift: staged through smem so every STG.128 is warp-contiguous.
#define JPB 1024          // j's per block
#define TPB 256           // threads per block

__global__ __launch_bounds__(TPB)
void pair_kernel(const float* __restrict__ cell,
                 float* __restrict__ dist_out,
                 float* __restrict__ shift_out, int n) {
    __shared__ float s_shift[JPB * 3];   // 12 KB

    int i = blockIdx.y;
    int base_j = blockIdx.x * JPB;
    int t = threadIdx.x;
    int j0 = base_j + t * 4;

    float c00 = __ldg(cell + 0), c01 = __ldg(cell + 1), c02 = __ldg(cell + 2);
    float c10 = __ldg(cell + 3), c11 = __ldg(cell + 4), c12 = __ldg(cell + 5);
    float c20 = __ldg(cell + 6), c21 = __ldg(cell + 7), c22 = __ldg(cell + 8);

    float fxi = g_fx[i], fyi = g_fy[i], fzi = g_fz[i];

    if (j0 < n) {
        float4 fxj = *reinterpret_cast<const float4*>(g_fx + j0);
        float4 fyj = *reinterpret_cast<const float4*>(g_fy + j0);
        float4 fzj = *reinterpret_cast<const float4*>(g_fz + j0);

        float fxs[4] = {fxj.x, fxj.y, fxj.z, fxj.w};
        float fys[4] = {fyj.x, fyj.y, fyj.z, fyj.w};
        float fzs[4] = {fzj.x, fzj.y, fzj.z, fzj.w};

        float dvals[4];
        float svals[12];

#pragma unroll
        for (int k = 0; k < 4; k++) {
            float dfx = fxs[k] - fxi;
            float dfy = fys[k] - fyi;
            float dfz = fzs[k] - fzi;

            float sx = -rintf(dfx);
            float sy = -rintf(dfy);
            float sz = -rintf(dfz);
            dfx += sx;
            dfy += sy;
            dfz += sz;

            float dx = dfx * c00 + dfy * c10 + dfz * c20;
            float dy = dfx * c01 + dfy * c11 + dfz * c21;
            float dz = dfx * c02 + dfy * c12 + dfz * c22;

            float d2 = dx * dx + dy * dy + dz * dz;
            bool m = (d2 > 0.0f) && (d2 < 25.0f);  // RC = 5.0
            dvals[k] = m ? sqrtf(d2) : 0.0f;
            svals[3 * k + 0] = sx;
            svals[3 * k + 1] = sy;
            svals[3 * k + 2] = sz;
        }

        // dist: warp-contiguous float4 store
        long long dbase = (long long)i * n + j0;
        *reinterpret_cast<float4*>(dist_out + dbase) =
            make_float4(dvals[0], dvals[1], dvals[2], dvals[3]);

        // shift: stage in smem, natural layout (12 consecutive floats/thread)
        float* sm = s_shift + t * 12;
        reinterpret_cast<float4*>(sm)[0] =
            make_float4(svals[0], svals[1], svals[2], svals[3]);
        reinterpret_cast<float4*>(sm)[1] =
            make_float4(svals[4], svals[5], svals[6], svals[7]);
        reinterpret_cast<float4*>(sm)[2] =
            make_float4(svals[8], svals[9], svals[10], svals[11]);
    }
    __syncthreads();

    // Coalesced shift writeback: store instruction s writes float4 (s*TPB + t)
    // => warp-contiguous 16B/thread addresses.
    int jcount = n - base_j;
    if (jcount > JPB) jcount = JPB;
    int nfloat = jcount * 3;                 // valid floats in this block region
    long long sbase = ((long long)i * n + base_j) * 3;  // float index into shift_out

#pragma unroll
    for (int s = 0; s < 3; s++) {
        int f = s * TPB + t;                 // float4 index within block region
        int fb = 4 * f;
        if (fb + 3 < nfloat) {
            float4 v = reinterpret_cast<const float4*>(s_shift)[f];
            *reinterpret_cast<float4*>(shift_out + sbase + fb) = v;
        } else if (fb < nfloat) {
            for (int c = 0; fb + c < nfloat && c < 4; c++)
                shift_out[sbase + fb + c] = s_shift[fb + c];
        }
    }
}

extern "C" void kernel_launch(void* const* d_in, const int* in_sizes, int n_in,
                              void* d_out, int out_size) {
    const float* coord = (const float*)d_in[0];   // (n, 3) float32
    const float* cell  = (const float*)d_in[1];   // (3, 3) float32
    const int*   elems = (const int*)d_in[2];     // (n,)   int32

    int n = in_sizes[0] / 3;

    float* out       = (float*)d_out;
    float* dist_out  = out + (long long)n * 4;      // n*n
    float* shift_out = dist_out + (long long)n * n; // n*n*3

    // 1) fused fractional coords + onehot
    {
        int threads = 256;
        int blocks = (n + threads - 1) / threads;
        frac_onehot_kernel<<<blocks, threads>>>(coord, cell, elems, out, n);
    }

    // 2) pairwise dist + shift
    {
        int jblocks = (n + JPB - 1) / JPB;
        dim3 grid(jblocks, n);
        pair_kernel<<<grid, TPB>>>(cell, dist_out, shift_out, n);
    }
}